// round 16
// baseline (speedup 1.0000x reference)
#include <cuda_runtime.h>
#include <cuda_fp16.h>
#include <math.h>
#include <stdint.h>

// Problem constants
#define BB 2
#define NN 2048
#define EE 1024
#define HH 16
#define HD 64
#define ROWS (BB*NN)          // 4096
#define FF (3*HH*HD)          // 3072

// Scratch (device globals; no allocations allowed)
__device__ __half g_kh[BB*HH*NN*HD];
__device__ __half g_qh[BB*HH*NN*HD];   // pre-scaled by 0.125
__device__ __half g_vth[BB*HH*HD*NN];  // V transposed: [bh][d][n]
__device__ __half g_sah[BB*NN*EE];
__device__ __half g_xh[ROWS*EE];       // x rounded to fp16
__device__ __half g_wqh[FF*EE];        // Wqkv transposed [F][E], fp16
__device__ __half g_woh[EE*EE];        // Wout transposed [n][k], fp16

// ---------------------------------------------------------------------------
// helpers
// ---------------------------------------------------------------------------
__device__ __forceinline__ uint32_t s2u(const void* p) {
    uint32_t a;
    asm("{ .reg .u64 t; cvta.to.shared.u64 t, %1; cvt.u32.u64 %0, t; }" : "=r"(a) : "l"(p));
    return a;
}
__device__ __forceinline__ uint32_t packh2(float lo, float hi) {
    __half2 h = __floats2half2_rn(lo, hi);
    return *(uint32_t*)&h;
}

#define CP_ASYNC16(dst_u32, src_ptr) \
    asm volatile("cp.async.cg.shared.global [%0], [%1], 16;" :: "r"(dst_u32), "l"(src_ptr))
#define CP_COMMIT() asm volatile("cp.async.commit_group;" ::: "memory")
#define CP_WAIT1()  asm volatile("cp.async.wait_group 1;" ::: "memory")
#define CP_WAIT0()  asm volatile("cp.async.wait_group 0;" ::: "memory")

#define LDSM_X4(r0, r1, r2, r3, addr) \
    asm volatile("ldmatrix.sync.aligned.m8n8.x4.shared.b16 {%0,%1,%2,%3}, [%4];" \
        : "=r"(r0), "=r"(r1), "=r"(r2), "=r"(r3) : "r"(addr))

__device__ __forceinline__ void mma_f16(float* c, const uint32_t* a, const uint32_t* b) {
    asm volatile(
        "mma.sync.aligned.m16n8k16.row.col.f32.f16.f16.f32 "
        "{%0,%1,%2,%3}, {%4,%5,%6,%7}, {%8,%9}, {%0,%1,%2,%3};"
        : "+f"(c[0]), "+f"(c[1]), "+f"(c[2]), "+f"(c[3])
        : "r"(a[0]), "r"(a[1]), "r"(a[2]), "r"(a[3]), "r"(b[0]), "r"(b[1]));
}

// ---------------------------------------------------------------------------
// Fused prep: x->fp16 (blocks [0,4096)); Wqkv transpose->fp16 ([4096,7168));
// Wout transpose->fp16 ([7168,8192)).
// ---------------------------------------------------------------------------
__global__ __launch_bounds__(256) void prep(const float* __restrict__ x,
                                            const float* __restrict__ Wq,
                                            const float* __restrict__ Wo)
{
    __shared__ float t[32][33];
    const int b = blockIdx.x;
    const int tid = threadIdx.x;

    if (b < 4096) {
        int i = b * 256 + tid;                        // float4 index
        float4 v = ((const float4*)x)[i];
        uint2 o;
        o.x = packh2(v.x, v.y);
        o.y = packh2(v.z, v.w);
        ((uint2*)g_xh)[i] = o;
        return;
    }

    const int tx = tid & 31;
    const int ty = tid >> 5;

    if (b < 7168) {
        const int bb = b - 4096;
        const int f0 = (bb % 96) * 32;
        const int e0 = (bb / 96) * 32;
        const int h = f0 / 192, fin = f0 % 192;
        const float* src = Wq + (size_t)h * EE * 192;
#pragma unroll
        for (int i = 0; i < 4; i++)
            t[ty + 8*i][tx] = src[(size_t)(e0 + ty + 8*i) * 192 + fin + tx];
        __syncthreads();
#pragma unroll
        for (int i = 0; i < 4; i++)
            g_wqh[(size_t)(f0 + ty + 8*i) * EE + e0 + tx] = __float2half_rn(t[tx][ty + 8*i]);
    } else {
        const int bb = b - 7168;
        const int n0 = (bb % 32) * 32;
        const int k0 = (bb / 32) * 32;
#pragma unroll
        for (int i = 0; i < 4; i++)
            t[ty + 8*i][tx] = Wo[(size_t)(k0 + ty + 8*i) * EE + n0 + tx];
        __syncthreads();
#pragma unroll
        for (int i = 0; i < 4; i++)
            g_woh[(size_t)(n0 + ty + 8*i) * EE + k0 + tx] = __float2half_rn(t[tx][ty + 8*i]);
    }
}

// ---------------------------------------------------------------------------
// fp16 HMMA GEMM mainloop: CTA 128x128, 256 threads, 8 warps of 64x32.
// BK=64 halves, cp.async THREE-stage pipeline (wait_group 1 -> 2 iters of
// latency tolerance), one __syncthreads per k-iter.
// smem stride 72 halves (144B): ldmatrix rows hit 8 distinct 16B chunks.
// Stage layout: stage s = [A (18432B) | B (18432B)] at s*36864.
// ---------------------------------------------------------------------------
#define SM_STRIDE 72
#define SM_MAT_B (128*SM_STRIDE*2)            // bytes per matrix per stage (18432)
#define SM_STAGE_B (2*SM_MAT_B)               // bytes per stage (36864)
#define GEMM_SMEM (3*SM_STAGE_B)              // 110592

__device__ __forceinline__ void hmma_mainloop(uint32_t smu,
                                              const __half* __restrict__ Ag,
                                              const __half* __restrict__ Bg,
                                              float acc[4][4][4])
{
    const int tid = threadIdx.x;

    const int lrow = tid >> 3;          // 0..31
    const int lc8  = tid & 7;           // 16B chunk (8 halves)

    auto issue = [&](int kt) {
        const int buf = kt % 3;
#pragma unroll
        for (int j = 0; j < 4; j++) {
            int row = lrow + j * 32;
            uint32_t soff = (uint32_t)(buf * SM_STAGE_B + row * (SM_STRIDE*2) + lc8 * 16);
            CP_ASYNC16(smu + soff, Ag + (size_t)row * EE + kt * 64 + lc8 * 8);
            CP_ASYNC16(smu + SM_MAT_B + soff, Bg + (size_t)row * EE + kt * 64 + lc8 * 8);
        }
        CP_COMMIT();
    };

    const int wid = tid >> 5;
    const int lane = tid & 31;
    const int wr = (wid & 1) * 64;
    const int wc = (wid >> 1) * 32;
    const int l7 = lane & 7;
    const int g1 = (lane >> 3) & 1;
    const int g2 = (lane >> 4) & 1;

    // ldmatrix per-thread base byte offsets
    const uint32_t aoff = (uint32_t)((wr + l7 + g1 * 8) * (SM_STRIDE*2) + g2 * 16);
    const uint32_t boff = (uint32_t)((wc + l7 + g2 * 8) * (SM_STRIDE*2) + g1 * 16);

    issue(0);
    issue(1);

#pragma unroll 1
    for (int kt = 0; kt < 16; kt++) {
        if (kt < 15) CP_WAIT1(); else CP_WAIT0();
        __syncthreads();
        if (kt < 14) issue(kt + 2);

        const uint32_t sb = smu + (uint32_t)((kt % 3) * SM_STAGE_B);
        const uint32_t aB = sb + aoff;
        const uint32_t bB = sb + SM_MAT_B + boff;

#pragma unroll
        for (int ks = 0; ks < 4; ks++) {
            const uint32_t kso = (uint32_t)(ks * 32);      // 16 halves
            uint32_t af[4][4], bf[4][2];
#pragma unroll
            for (int i = 0; i < 4; i++)
                LDSM_X4(af[i][0], af[i][1], af[i][2], af[i][3],
                        aB + (uint32_t)(i * 16 * SM_STRIDE * 2) + kso);
            LDSM_X4(bf[0][0], bf[0][1], bf[1][0], bf[1][1], bB + kso);
            LDSM_X4(bf[2][0], bf[2][1], bf[3][0], bf[3][1],
                    bB + (uint32_t)(16 * SM_STRIDE * 2) + kso);
#pragma unroll
            for (int i = 0; i < 4; i++)
#pragma unroll
                for (int j = 0; j < 4; j++)
                    mma_f16(acc[i][j], af[i], bf[j]);
        }
    }
}

// ---------------------------------------------------------------------------
// QKV GEMM: + bias, fp16-round, scatter: K->g_kh, Q->g_qh (x0.125), V->g_vth^T
// ---------------------------------------------------------------------------
__global__ __launch_bounds__(256, 2) void qkv_mma(const float* __restrict__ bqkv)
{
    extern __shared__ char smc[];
    const uint32_t smu = s2u(smc);

    const int c0 = blockIdx.x * 128;
    const int r0 = blockIdx.y * 128;

    float acc[4][4][4];
#pragma unroll
    for (int i = 0; i < 4; i++)
#pragma unroll
        for (int j = 0; j < 4; j++)
#pragma unroll
            for (int t = 0; t < 4; t++) acc[i][j][t] = 0.f;

    hmma_mainloop(smu, g_xh + (size_t)r0 * EE, g_wqh + (size_t)c0 * EE, acc);

    const int wid = threadIdx.x >> 5;
    const int lane = threadIdx.x & 31;
    const int qr = lane >> 2, qc = lane & 3;
    const int wr = (wid & 1) * 64;
    const int wc = (wid >> 1) * 32;

#pragma unroll
    for (int i = 0; i < 4; i++) {
#pragma unroll
        for (int j = 0; j < 4; j++) {
            const int colF = c0 + wc + j * 8 + qc * 2;
            const int h = colF / 192, f = colF % 192;
            const int seg = f >> 6, fo = f & 63;
            const float b0 = bqkv[colF], b1 = bqkv[colF + 1];
#pragma unroll
            for (int half = 0; half < 2; half++) {
                const int r = r0 + wr + i * 16 + qr + half * 8;
                const int bb = r >> 11;
                const int n_ = r & (NN - 1);
                float v0 = acc[i][j][half * 2 + 0] + b0;
                float v1 = acc[i][j][half * 2 + 1] + b1;
                if (seg == 2) {
                    size_t vb = ((size_t)(bb * HH + h) * HD + fo) * NN + n_;
                    g_vth[vb]      = __float2half_rn(v0);
                    g_vth[vb + NN] = __float2half_rn(v1);
                } else {
                    size_t off = ((size_t)(bb * HH + h) * NN + n_) * HD + fo;
                    if (seg == 0) {
                        *(uint32_t*)(g_kh + off) = packh2(v0, v1);
                    } else {
                        *(uint32_t*)(g_qh + off) = packh2(v0 * 0.125f, v1 * 0.125f);
                    }
                }
            }
        }
    }
}

// ---------------------------------------------------------------------------
// Output GEMM: out = g_sah @ Wout + bout (fp32 out)
// ---------------------------------------------------------------------------
__global__ __launch_bounds__(256, 2) void out_mma(const float* __restrict__ bout,
                                                  float* __restrict__ out)
{
    extern __shared__ char smc[];
    const uint32_t smu = s2u(smc);

    const int c0 = blockIdx.x * 128;
    const int r0 = blockIdx.y * 128;

    float acc[4][4][4];
#pragma unroll
    for (int i = 0; i < 4; i++)
#pragma unroll
        for (int j = 0; j < 4; j++)
#pragma unroll
            for (int t = 0; t < 4; t++) acc[i][j][t] = 0.f;

    hmma_mainloop(smu, g_sah + (size_t)r0 * EE, g_woh + (size_t)c0 * EE, acc);

    const int wid = threadIdx.x >> 5;
    const int lane = threadIdx.x & 31;
    const int qr = lane >> 2, qc = lane & 3;
    const int wr = (wid & 1) * 64;
    const int wc = (wid >> 1) * 32;

#pragma unroll
    for (int i = 0; i < 4; i++) {
#pragma unroll
        for (int j = 0; j < 4; j++) {
            const int col = c0 + wc + j * 8 + qc * 2;
            const float b0 = bout[col], b1 = bout[col + 1];
#pragma unroll
            for (int half = 0; half < 2; half++) {
                const size_t r = (size_t)(r0 + wr + i * 16 + qr + half * 8);
                float2 o;
                o.x = acc[i][j][half * 2 + 0] + b0;
                o.y = acc[i][j][half * 2 + 1] + b1;
                *(float2*)(out + r * EE + col) = o;
            }
        }
    }
}

// ---------------------------------------------------------------------------
// Causal flash attention, fp16 HMMA, online softmax, 3-stage cp.async.
// CTA: 128 q-rows, 256 threads, 8 warps x 16 rows.
// K smem [j][k] (64x72h), V^T smem [d][j] (64x72h).
// Stage layout: stage s = [K (9216B) | V (9216B)] at s*18432.
// ---------------------------------------------------------------------------
#define ASW 72
#define ATT_MAT_B (64*ASW*2)                 // 9216 bytes
#define ATT_STAGE_B (2*ATT_MAT_B)            // 18432
#define ATT_SMEM (3*ATT_STAGE_B)             // 55296

__global__ __launch_bounds__(256, 2) void attn_mma()
{
    extern __shared__ char smc[];
    const uint32_t smu = s2u(smc);

    const int tid  = threadIdx.x;
    const int wid  = tid >> 5, lane = tid & 31;
    const int qr   = lane >> 2, qc = lane & 3;
    const int qt   = (int)gridDim.x - 1 - (int)blockIdx.x;   // heavy first
    const int bh   = blockIdx.y;
    const int wr   = wid * 16;

    const int l7 = lane & 7;
    const int g1 = (lane >> 3) & 1;
    const int g2 = (lane >> 4) & 1;
    const uint32_t boff = (uint32_t)((l7 + g2 * 8) * (ASW*2) + g1 * 16);

    const __half* kg = g_kh  + (size_t)bh * NN * HD;
    const __half* vg = g_vth + (size_t)bh * HD * NN;

    // Q A-fragments (pre-scaled fp16): 4 k16 chunks x 4 regs
    uint32_t qa[4][4];
    {
        const __half* qb = g_qh + ((size_t)bh * NN + qt * 128 + wr) * HD;
#pragma unroll
        for (int ks = 0; ks < 4; ks++) {
            qa[ks][0] = *(const uint32_t*)(qb + qr * 64 + ks * 16 + 2 * qc);
            qa[ks][1] = *(const uint32_t*)(qb + (qr + 8) * 64 + ks * 16 + 2 * qc);
            qa[ks][2] = *(const uint32_t*)(qb + qr * 64 + ks * 16 + 2 * qc + 8);
            qa[ks][3] = *(const uint32_t*)(qb + (qr + 8) * 64 + ks * 16 + 2 * qc + 8);
        }
    }

    float o[8][4];
#pragma unroll
    for (int nt = 0; nt < 8; nt++)
#pragma unroll
        for (int t = 0; t < 4; t++) o[nt][t] = 0.f;
    float m0 = -INFINITY, m1 = -INFINITY, l0 = 0.f, l1 = 0.f;

    const unsigned FULL = 0xffffffffu;
    const int jt_end = 2 * qt + 1;

    // cp.async one (K,V) stage: 64 rows x 64 halves each
    auto issue = [&](int jt) {
        const int buf = jt % 3;
#pragma unroll
        for (int i = 0; i < 2; i++) {
            int idx = tid + i * 256;            // 0..511
            int row = idx >> 3;                 // 0..63
            int c8  = idx & 7;
            uint32_t soff = (uint32_t)(buf * ATT_STAGE_B + row * (ASW*2) + c8 * 16);
            CP_ASYNC16(smu + soff, kg + (size_t)(jt * 64 + row) * HD + c8 * 8);
            CP_ASYNC16(smu + ATT_MAT_B + soff, vg + (size_t)row * NN + jt * 64 + c8 * 8);
        }
        CP_COMMIT();
    };

    issue(0);
    issue(1);        // jt_end >= 1 always

#pragma unroll 1
    for (int jt = 0; jt <= jt_end; jt++) {
        if (jt < jt_end) CP_WAIT1(); else CP_WAIT0();
        __syncthreads();
        if (jt + 2 <= jt_end) issue(jt + 2);

        const uint32_t sb = smu + (uint32_t)((jt % 3) * ATT_STAGE_B);
        const uint32_t kB = sb + boff;
        const uint32_t vB = sb + ATT_MAT_B + boff;

        const bool active = (jt * 64 <= qt * 128 + wr + 15);
        if (active) {
            // ---- S = Q K^T ----
            float s[8][4];
#pragma unroll
            for (int nt = 0; nt < 8; nt++)
#pragma unroll
                for (int t = 0; t < 4; t++) s[nt][t] = 0.f;

#pragma unroll
            for (int ks = 0; ks < 4; ks++) {
                const uint32_t kso = (uint32_t)(ks * 32);
                uint32_t bf[8][2];
#pragma unroll
                for (int jp = 0; jp < 4; jp++)
                    LDSM_X4(bf[2*jp][0], bf[2*jp][1], bf[2*jp+1][0], bf[2*jp+1][1],
                            kB + (uint32_t)(jp * 16 * ASW * 2) + kso);
#pragma unroll
                for (int nt = 0; nt < 8; nt++)
                    mma_f16(s[nt], qa[ks], bf[nt]);
            }

            // ---- causal mask ----
            if (jt >= 2 * qt) {
                const int rg0 = qt * 128 + wr + qr;
                const int rg1 = rg0 + 8;
#pragma unroll
                for (int nt = 0; nt < 8; nt++) {
                    const int jg = jt * 64 + nt * 8 + 2 * qc;
                    if (jg > rg0)     s[nt][0] = -INFINITY;
                    if (jg + 1 > rg0) s[nt][1] = -INFINITY;
                    if (jg > rg1)     s[nt][2] = -INFINITY;
                    if (jg + 1 > rg1) s[nt][3] = -INFINITY;
                }
            }

            // ---- online softmax (rows qr / qr+8; quad shfl) ----
            float mt0 = s[0][0], mt1 = s[0][2];
#pragma unroll
            for (int nt = 0; nt < 8; nt++) {
                mt0 = fmaxf(mt0, fmaxf(s[nt][0], s[nt][1]));
                mt1 = fmaxf(mt1, fmaxf(s[nt][2], s[nt][3]));
            }
            mt0 = fmaxf(mt0, __shfl_xor_sync(FULL, mt0, 1));
            mt0 = fmaxf(mt0, __shfl_xor_sync(FULL, mt0, 2));
            mt1 = fmaxf(mt1, __shfl_xor_sync(FULL, mt1, 1));
            mt1 = fmaxf(mt1, __shfl_xor_sync(FULL, mt1, 2));

            const float mn0 = fmaxf(m0, mt0);
            const float mn1 = fmaxf(m1, mt1);
            const float c0_ = __expf(m0 - mn0);
            const float c1_ = __expf(m1 - mn1);

            float ps0 = 0.f, ps1 = 0.f;
#pragma unroll
            for (int nt = 0; nt < 8; nt++) {
                s[nt][0] = __expf(s[nt][0] - mn0);
                s[nt][1] = __expf(s[nt][1] - mn0);
                s[nt][2] = __expf(s[nt][2] - mn1);
                s[nt][3] = __expf(s[nt][3] - mn1);
                ps0 += s[nt][0] + s[nt][1];
                ps1 += s[nt][2] + s[nt][3];
            }
            ps0 += __shfl_xor_sync(FULL, ps0, 1);
            ps0 += __shfl_xor_sync(FULL, ps0, 2);
            ps1 += __shfl_xor_sync(FULL, ps1, 1);
            ps1 += __shfl_xor_sync(FULL, ps1, 2);

            l0 = l0 * c0_ + ps0;  m0 = mn0;
            l1 = l1 * c1_ + ps1;  m1 = mn1;
#pragma unroll
            for (int nt = 0; nt < 8; nt++) {
                o[nt][0] *= c0_;  o[nt][1] *= c0_;
                o[nt][2] *= c1_;  o[nt][3] *= c1_;
            }

            // ---- O += P V : P packs C-frag -> A-frag in registers ----
#pragma unroll
            for (int ks = 0; ks < 4; ks++) {
                uint32_t af[4];
                af[0] = packh2(s[2*ks][0],   s[2*ks][1]);
                af[1] = packh2(s[2*ks][2],   s[2*ks][3]);
                af[2] = packh2(s[2*ks+1][0], s[2*ks+1][1]);
                af[3] = packh2(s[2*ks+1][2], s[2*ks+1][3]);
                const uint32_t kso = (uint32_t)(ks * 32);
                uint32_t bf[8][2];
#pragma unroll
                for (int dp = 0; dp < 4; dp++)
                    LDSM_X4(bf[2*dp][0], bf[2*dp][1], bf[2*dp+1][0], bf[2*dp+1][1],
                            vB + (uint32_t)(dp * 16 * ASW * 2) + kso);
#pragma unroll
                for (int nt = 0; nt < 8; nt++)
                    mma_f16(o[nt], af, bf[nt]);
            }
        }
    }

    // ---- epilogue: normalize + scatter to g_sah [B, N, E] ----
    const float il0 = 1.0f / l0;
    const float il1 = 1.0f / l1;
    const int b = bh >> 4;
    const int h = bh & 15;
    const int n0 = qt * 128 + wr + qr;
    __half* o0 = g_sah + ((size_t)b * NN + n0) * EE + h * HD;
    __half* o1 = o0 + (size_t)8 * EE;
#pragma unroll
    for (int nt = 0; nt < 8; nt++) {
        const int d = nt * 8 + 2 * qc;
        *(uint32_t*)(o0 + d) = packh2(o[nt][0] * il0, o[nt][1] * il0);
        *(uint32_t*)(o1 + d) = packh2(o[nt][2] * il1, o[nt][3] * il1);
    }
}

// ---------------------------------------------------------------------------
extern "C" void kernel_launch(void* const* d_in, const int* in_sizes, int n_in,
                              void* d_out, int out_size)
{
    const float* x    = (const float*)d_in[0];
    const float* Wqkv = (const float*)d_in[1];
    const float* bqkv = (const float*)d_in[2];
    const float* Wout = (const float*)d_in[3];
    const float* bout = (const float*)d_in[4];
    float* out = (float*)d_out;

    // 0) fused prep: round x + transpose weights to fp16
    prep<<<8192, 256>>>(x, Wqkv, Wout);

    // 1) QKV projection (fp16 HMMA, 3-stage)
    cudaFuncSetAttribute(qkv_mma, cudaFuncAttributeMaxDynamicSharedMemorySize, GEMM_SMEM);
    qkv_mma<<<dim3(FF / 128, ROWS / 128), 256, GEMM_SMEM>>>(bqkv);

    // 2) Causal attention (fp16 HMMA, 3-stage)
    cudaFuncSetAttribute(attn_mma, cudaFuncAttributeMaxDynamicSharedMemorySize, ATT_SMEM);
    attn_mma<<<dim3(NN / 128, BB * HH), 256, ATT_SMEM>>>();

    // 3) Output projection (fp16 HMMA, 3-stage)
    cudaFuncSetAttribute(out_mma, cudaFuncAttributeMaxDynamicSharedMemorySize, GEMM_SMEM);
    out_mma<<<dim3(EE / 128, ROWS / 128), 256, GEMM_SMEM>>>(bout, out);
}